// round 11
// baseline (speedup 1.0000x reference)
#include <cuda_runtime.h>

static constexpr int B = 4096;
static constexpr int K = 1024;
static constexpr int C = 10;
static constexpr int M = 19;

// Block = 32 b x 512 k, 256 threads. Thread = (bg 0..7, kc 0..31):
// owns 4 consecutive b (int4 loads). Warp k-row = 8 lanes x 16B = 128B line.
static constexpr int NB      = 32;
static constexpr int NKC     = 32;
static constexpr int THREADS = 8 * NKC;         // 256
static constexpr int KSPLIT  = 2;
static constexpr int KBLK    = K / KSPLIT;      // 512
static constexpr int KCHUNK  = KBLK / NKC;      // 16 iterations (64 samples/thread)

static constexpr int BSTR    = THREADS + 1;     // 257

static constexpr int LBIN_F  = M * BSTR;              // 4883 floats per l-array
static constexpr int TBL_F   = 4 * 100 * 8;           // 3200 floats
static constexpr int SMEM_B  = (4 * LBIN_F + TBL_F) * 4;  // ~90.9 KB

__device__ float g_scratch[B * M];     // zero-init; re-zeroed by finishing block
__device__ int   g_ticket[B / NB];     // zero-init; reset by finishing block

__global__ __launch_bounds__(THREADS, 2)
void ised_kernel(const float* __restrict__ x1,
                 const float* __restrict__ x2,
                 const int*   __restrict__ idx1,
                 const int*   __restrict__ idx2,
                 float*       __restrict__ out)
{
    extern __shared__ float sm[];
    // Four DISJOINT bin arrays (restrict => compiler may interleave their RMWs)
    float* __restrict__ bins0 = sm;
    float* __restrict__ bins1 = sm + 1 * LBIN_F;
    float* __restrict__ bins2 = sm + 2 * LBIN_F;
    float* __restrict__ bins3 = sm + 3 * LBIN_F;
    float* __restrict__ table = sm + 4 * LBIN_F;   // [l][ij][bg]
    __shared__ float rowsum[NB][M + 1];
    __shared__ int   s_last;

    const int tid = threadIdx.x;
    const int b0  = blockIdx.x * NB;
    const int k0  = blockIdx.y * KBLK;

    // ---- Tables: table[l*800 + ij*8 + bg] = x1[b0+bg*4+l, i] * x2[..., j] ----
    for (int e = tid; e < 4 * 100 * 8; e += THREADS) {
        const int bg = e & 7;
        const int ij = (e >> 3) % 100;
        const int l  = e / 800;
        const int i  = ij / 10;
        const int j  = ij - i * 10;
        const int b  = b0 + bg * 4 + l;
        table[e] = __ldg(&x1[b * C + i]) * __ldg(&x2[b * C + j]);
    }
    for (int e = tid; e < LBIN_F; e += THREADS) {
        bins0[e] = 0.0f;
        bins1[e] = 0.0f;
        bins2[e] = 0.0f;
        bins3[e] = 0.0f;
    }
    __syncthreads();

    // ---- Main loop: two int4 loads -> 4 samples/iter, 4 independent RMW chains ----
    const int bg = tid & 7;
    const int kc = tid >> 3;
    const int b  = b0 + bg * 4;                 // 16B aligned

    const int4* __restrict__ p1 =
        (const int4*)(idx1 + (size_t)(k0 + kc * KCHUNK) * B + b);
    const int4* __restrict__ p2 =
        (const int4*)(idx2 + (size_t)(k0 + kc * KCHUNK) * B + b);

    #pragma unroll 4
    for (int k = 0; k < KCHUNK; k++) {
        const int4 a = __ldg(&p1[(size_t)k * (B / 4)]);
        const int4 c = __ldg(&p2[(size_t)k * (B / 4)]);

        // Batch the 4 table reads first (read-only array, hoistable)
        const float t0 = table[0 * 800 + (a.x * 10 + c.x) * 8 + bg];
        const float t1 = table[1 * 800 + (a.y * 10 + c.y) * 8 + bg];
        const float t2 = table[2 * 800 + (a.z * 10 + c.z) * 8 + bg];
        const float t3 = table[3 * 800 + (a.w * 10 + c.w) * 8 + bg];

        // 4 RMWs into 4 restrict-disjoint arrays -> chains overlap
        bins0[(a.x + c.x) * BSTR + tid] += t0;
        bins1[(a.y + c.y) * BSTR + tid] += t1;
        bins2[(a.z + c.z) * BSTR + tid] += t2;
        bins3[(a.w + c.w) * BSTR + tid] += t3;
    }
    __syncthreads();

    // ---- Reduce 32 kc-partials per (b, m); push to L2 scratch ----
    for (int e = tid; e < NB * M; e += THREADS) {
        const int bl  = e % NB;
        const int m   = e / NB;
        const int bg2 = bl >> 2;
        const int l   = bl & 3;
        const float* __restrict__ src =
            (l == 0) ? bins0 : (l == 1) ? bins1 : (l == 2) ? bins2 : bins3;
        float v = 0.0f;
        #pragma unroll
        for (int c2 = 0; c2 < NKC; c2++) {
            v += src[m * BSTR + c2 * 8 + bg2];
        }
        atomicAdd(&g_scratch[(b0 + bl) * M + m], v);
    }

    // ---- Ticket: last KSPLIT-block for this row-group finishes the rows ----
    __threadfence();
    __syncthreads();
    if (tid == 0) {
        s_last = (atomicAdd(&g_ticket[blockIdx.x], 1) == KSPLIT - 1);
    }
    __syncthreads();
    if (!s_last) return;

    for (int e = tid; e < NB * M; e += THREADS) {
        const int bl = e % NB;
        const int m  = e / NB;
        rowsum[bl][m] = __ldcg(&g_scratch[(b0 + bl) * M + m]);
    }
    __syncthreads();

    if (tid < NB) {
        float sq = 0.0f;
        #pragma unroll
        for (int m = 0; m < M; m++) {
            const float v = rowsum[tid][m];
            sq += v * v;
        }
        rowsum[tid][M] = 1.0f / fmaxf(sqrtf(sq), 1e-12f);
    }
    __syncthreads();

    for (int e = tid; e < NB * M; e += THREADS) {
        const int bl = e % NB;
        const int m  = e / NB;
        out[(size_t)(b0 + bl) * M + m] = rowsum[bl][m] * rowsum[bl][M];
        __stcg(&g_scratch[(b0 + bl) * M + m], 0.0f);   // reset for next replay
    }
    if (tid == 0) {
        g_ticket[blockIdx.x] = 0;
    }
}

extern "C" void kernel_launch(void* const* d_in, const int* in_sizes, int n_in,
                              void* d_out, int out_size)
{
    const float* x1   = (const float*)d_in[0];   // [B, C]
    const float* x2   = (const float*)d_in[1];   // [B, C]
    const int*   idx1 = (const int*)d_in[2];     // [K, B]
    const int*   idx2 = (const int*)d_in[3];     // [K, B]
    float*       out  = (float*)d_out;           // [B, M]

    (void)in_sizes; (void)n_in; (void)out_size;

    cudaFuncSetAttribute(ised_kernel,
                         cudaFuncAttributeMaxDynamicSharedMemorySize, SMEM_B);

    dim3 grid(B / NB, KSPLIT);
    ised_kernel<<<grid, THREADS, SMEM_B>>>(x1, x2, idx1, idx2, out);
}